// round 17
// baseline (speedup 1.0000x reference)
#include <cuda_runtime.h>
#include <cstdint>

// Masked mean over first xs_len[b] rows of xs[b]: out[b][d] = sum_{s<L} xs[b][s][d] / L
// xs: [16, 4096, 512] f32, xs_len: [16] (int32 OR int64 -- decoded at runtime), out: [16, 512] f32
// Structure: memset(out, 0) graph node + ONE kernel. Each split block scales
// its partial by 1/L and RED.ADD.F32s it straight into out. No scratch, no
// finalize pass, no arrival protocol.

#define B 16
#define S 4096
#define D 512
#define D4 (D / 4)                   // 128 float4 per row
#define SPLIT 64
#define ROWS_PER_SPLIT (S / SPLIT)   // 64

// Robust length decode: int64 value lies in [1, S]; an int32 buffer read as
// int64 packs two lengths (both >= 1) and falls outside [1, S].
__device__ __forceinline__ int decode_len(const void* xs_len, int b) {
    long long v64 = ((const long long*)xs_len)[b];
    if (v64 >= 1 && v64 <= (long long)S) return (int)v64;
    return ((const int*)xs_len)[b];
}

// No-return global f32 reduction add (RED.E.ADD.F32) -- fire and forget.
__device__ __forceinline__ void red_add_f32(float* p, float v) {
    asm volatile("red.global.add.f32 [%0], %1;" :: "l"(p), "f"(v) : "memory");
}

// K1: grid (SPLIT, B), 256 threads arranged as (half, col):
//   col  = t & 127  -> float4 column
//   half = t >> 7   -> rows s0+half, s0+half+2, ... (stride 2)
// Each half accumulates up to 32 contiguous-split rows with 8 independent
// LDG.128 in flight, scales by 1/L, and REDs its 4 floats into out.
__global__ void __launch_bounds__(256, 6)
mean_partial_kernel(const float* __restrict__ xs,
                    const void* __restrict__ xs_len,
                    float* __restrict__ out) {
    const int sp   = blockIdx.x;
    const int b    = blockIdx.y;
    const int t    = threadIdx.x;
    const int col  = t & (D4 - 1);
    const int half = t >> 7;

    const int L  = decode_len(xs_len, b);
    const int s0 = sp * ROWS_PER_SPLIT;
    if (s0 >= L) return;                 // uniform per block: contributes nothing
    int s1 = s0 + ROWS_PER_SPLIT;
    if (s1 > L) s1 = L;

    const float4* __restrict__ base =
        reinterpret_cast<const float4*>(xs + (size_t)b * S * D) + col;

    float4 acc = make_float4(0.f, 0.f, 0.f, 0.f);

    int s = s0 + half;
    // 8 independent LDG.128 in flight (rows s, s+2, ..., s+14)
    for (; s + 14 < s1; s += 16) {
        float4 v0 = base[(size_t)(s +  0) * D4];
        float4 v1 = base[(size_t)(s +  2) * D4];
        float4 v2 = base[(size_t)(s +  4) * D4];
        float4 v3 = base[(size_t)(s +  6) * D4];
        float4 v4 = base[(size_t)(s +  8) * D4];
        float4 v5 = base[(size_t)(s + 10) * D4];
        float4 v6 = base[(size_t)(s + 12) * D4];
        float4 v7 = base[(size_t)(s + 14) * D4];
        acc.x += (v0.x + v1.x) + (v2.x + v3.x) + (v4.x + v5.x) + (v6.x + v7.x);
        acc.y += (v0.y + v1.y) + (v2.y + v3.y) + (v4.y + v5.y) + (v6.y + v7.y);
        acc.z += (v0.z + v1.z) + (v2.z + v3.z) + (v4.z + v5.z) + (v6.z + v7.z);
        acc.w += (v0.w + v1.w) + (v2.w + v3.w) + (v4.w + v5.w) + (v6.w + v7.w);
    }
    for (; s < s1; s += 2) {
        float4 v = base[(size_t)s * D4];
        acc.x += v.x; acc.y += v.y; acc.z += v.z; acc.w += v.w;
    }

    // Scale by 1/L (identical value in every block of batch b) and reduce
    // directly into the output. Both halves add independently -- commutative.
    const float inv = 1.0f / (float)L;
    float* o = out + (size_t)b * D + col * 4;
    red_add_f32(o + 0, acc.x * inv);
    red_add_f32(o + 1, acc.y * inv);
    red_add_f32(o + 2, acc.z * inv);
    red_add_f32(o + 3, acc.w * inv);
}

extern "C" void kernel_launch(void* const* d_in, const int* in_sizes, int n_in,
                              void* d_out, int out_size) {
    const float* xs = (const float*)d_in[0];
    const void* xs_len = d_in[1];
    float* out = (float*)d_out;

    // Zero the 32 KB output (graph memset node), then accumulate into it.
    cudaMemsetAsync(d_out, 0, (size_t)out_size * sizeof(float), 0);

    dim3 grid(SPLIT, B);
    mean_partial_kernel<<<grid, 256>>>(xs, xs_len, out);
}